// round 17
// baseline (speedup 1.0000x reference)
#include <cuda_runtime.h>
#include <cuda_bf16.h>
#include <mma.h>
#include <cstdint>

using namespace nvcuda;

// GCNAggregator fused warp-specialized pipeline, 2 CTAs/SM:
//   producer warps 0-7 : gather + mean + bf16 hi/lo split -> smem A (2 bufs)
//   consumer warps 8-15: 3-term bf16-split WMMA + relu -> out
// 2048 tiles of 16 rows over 296 CTAs (max 7 vs avg 6.92).

#define D_DIM 128
#define S_SAMPLES 25
#define N_NODES 100000
#define N_ROWS 32768
#define TILE_ROWS 16
#define N_TILES (N_ROWS / TILE_ROWS)   // 2048
#define THREADS 512
#define GRID 296
#define NBUF 2

#define LDS_A 136                      // bf16 stride (272B rows)
#define SA_ELEMS (TILE_ROWS * LDS_A)   // 2176
#define SW_ELEMS (D_DIM * LDS_A)       // 17408
// smem: W hi/lo + 2 bufs * A hi/lo = (2*17408 + 2*2*2176)*2 = 87,040 B
#define SMEM_BYTES ((2 * SW_ELEMS + NBUF * 2 * SA_ELEMS) * 2)

#define BAR_SYNC(id)   asm volatile("bar.sync %0, %1;"   :: "r"(id), "n"(THREADS) : "memory")
#define BAR_ARRIVE(id) asm volatile("bar.arrive %0, %1;" :: "r"(id), "n"(THREADS) : "memory")

// Gather one row's 25 features and mean them. Index loads are int4 from
// (sample + row*25 - OFF), OFF = row & 3 (compile-time per call site), so
// every load is 16B-aligned; elements outside [0,25) are discarded.
template <int OFF>
__device__ __forceinline__ float4 gather_row(const int* __restrict__ idx_al,
                                             const float* __restrict__ features,
                                             int k0)
{
    float4 acc = make_float4(0.f, 0.f, 0.f, 0.f);
    const int4* ip = reinterpret_cast<const int4*>(idx_al);
    #pragma unroll
    for (int i = 0; i < 7; i++) {
        const int4 q = __ldg(&ip[i]);
        const int e0 = q.x, e1 = q.y, e2 = q.z, e3 = q.w;
        #pragma unroll
        for (int e = 0; e < 4; e++) {
            const int g = 4 * i + e - OFF;          // sample index
            if (g >= 0 && g < S_SAMPLES) {
                int node = (e == 0) ? e0 : (e == 1) ? e1 : (e == 2) ? e2 : e3;
                node = min(max(node, 0), N_NODES - 1);
                const float4 v = *reinterpret_cast<const float4*>(
                    &features[(long long)node * D_DIM + k0]);
                acc.x += v.x; acc.y += v.y; acc.z += v.z; acc.w += v.w;
            }
        }
    }
    const float inv = 1.0f / (float)S_SAMPLES;
    acc.x *= inv; acc.y *= inv; acc.z *= inv; acc.w *= inv;
    return acc;
}

__global__ __launch_bounds__(THREADS, 2)
void gcn_fused_kernel(const float* __restrict__ features,
                      const int* __restrict__ sample,
                      const float* __restrict__ W,
                      float* __restrict__ out)
{
    extern __shared__ __nv_bfloat16 smem[];
    __nv_bfloat16* sWhi = smem;                     // [128][136]
    __nv_bfloat16* sWlo = smem + SW_ELEMS;
    __nv_bfloat16* sA   = smem + 2 * SW_ELEMS;      // [NBUF][hi/lo][16][136]

    const int tid  = threadIdx.x;
    const int wid  = tid >> 5;       // 0..15
    const int lane = tid & 31;

    // ---- Stage W once: fp32 -> bf16 hi/lo ----
    #pragma unroll
    for (int i = 0; i < 8; i++) {
        const int idx = tid + i * THREADS;        // 0..4095 float4
        const int k   = idx >> 5;
        const int n0  = (idx & 31) * 4;
        const float4 v = *reinterpret_cast<const float4*>(&W[k * D_DIM + n0]);
        const __nv_bfloat16 hx = __float2bfloat16(v.x);
        const __nv_bfloat16 hy = __float2bfloat16(v.y);
        const __nv_bfloat16 hz = __float2bfloat16(v.z);
        const __nv_bfloat16 hw = __float2bfloat16(v.w);
        *reinterpret_cast<__nv_bfloat162*>(&sWhi[k * LDS_A + n0]) =
            __nv_bfloat162(hx, hy);
        *reinterpret_cast<__nv_bfloat162*>(&sWhi[k * LDS_A + n0 + 2]) =
            __nv_bfloat162(hz, hw);
        *reinterpret_cast<__nv_bfloat162*>(&sWlo[k * LDS_A + n0]) =
            __nv_bfloat162(__float2bfloat16(v.x - __bfloat162float(hx)),
                           __float2bfloat16(v.y - __bfloat162float(hy)));
        *reinterpret_cast<__nv_bfloat162*>(&sWlo[k * LDS_A + n0 + 2]) =
            __nv_bfloat162(__float2bfloat16(v.z - __bfloat162float(hz)),
                           __float2bfloat16(v.w - __bfloat162float(hw)));
    }
    __syncthreads();

    if (wid < 8) {
        // ============ PRODUCER: 8 warps x 2 rows per 16-row tile ============
        const int k0 = lane * 4;
        int it = 0;
        for (int t = blockIdx.x; t < N_TILES; t += GRID, ++it) {
            const int buf = it & 1;
            __nv_bfloat16* aHi = sA + buf * 2 * SA_ELEMS;
            __nv_bfloat16* aLo = aHi + SA_ELEMS;

            if (it >= NBUF) BAR_SYNC(NBUF + 1 + buf);   // wait buffer empty

            #pragma unroll
            for (int r = 0; r < 2; r++) {
                const int row = t * TILE_ROWS + wid * 2 + r;
                const int off = (wid * 2 + r) & 3;      // uniform per warp
                const int* idx_al = sample + (long long)row * S_SAMPLES - off;

                float4 acc;
                switch (off) {
                    case 0: acc = gather_row<0>(idx_al, features, k0); break;
                    case 1: acc = gather_row<1>(idx_al, features, k0); break;
                    case 2: acc = gather_row<2>(idx_al, features, k0); break;
                    default: acc = gather_row<3>(idx_al, features, k0); break;
                }

                const __nv_bfloat16 hx = __float2bfloat16(acc.x);
                const __nv_bfloat16 hy = __float2bfloat16(acc.y);
                const __nv_bfloat16 hz = __float2bfloat16(acc.z);
                const __nv_bfloat16 hw = __float2bfloat16(acc.w);
                const int soff = (wid * 2 + r) * LDS_A + k0;
                *reinterpret_cast<__nv_bfloat162*>(&aHi[soff]) =
                    __nv_bfloat162(hx, hy);
                *reinterpret_cast<__nv_bfloat162*>(&aHi[soff + 2]) =
                    __nv_bfloat162(hz, hw);
                *reinterpret_cast<__nv_bfloat162*>(&aLo[soff]) =
                    __nv_bfloat162(
                        __float2bfloat16(acc.x - __bfloat162float(hx)),
                        __float2bfloat16(acc.y - __bfloat162float(hy)));
                *reinterpret_cast<__nv_bfloat162*>(&aLo[soff + 2]) =
                    __nv_bfloat162(
                        __float2bfloat16(acc.z - __bfloat162float(hz)),
                        __float2bfloat16(acc.w - __bfloat162float(hw)));
            }
            __threadfence_block();
            BAR_ARRIVE(1 + buf);                    // signal buffer full
        }
    } else {
        // ============ CONSUMER: 8 warps x (16 rows x 16 cols) ============
        const int cw = wid - 8;                 // 0..7
        const int wc = cw * 16;                 // col base

        int it = 0;
        for (int t = blockIdx.x; t < N_TILES; t += GRID, ++it) {
            const int buf = it & 1;
            const __nv_bfloat16* aHi = sA + buf * 2 * SA_ELEMS;

            BAR_SYNC(1 + buf);                  // wait buffer full

            wmma::fragment<wmma::accumulator, 16, 16, 16, float> acc;
            wmma::fill_fragment(acc, 0.0f);

            #pragma unroll
            for (int ks = 0; ks < D_DIM / 16; ks++) {
                wmma::fragment<wmma::matrix_a, 16, 16, 16, __nv_bfloat16,
                               wmma::row_major> fAhi, fAlo;
                wmma::fragment<wmma::matrix_b, 16, 16, 16, __nv_bfloat16,
                               wmma::row_major> fBhi, fBlo;

                const __nv_bfloat16* pa = &aHi[ks * 16];
                wmma::load_matrix_sync(fAhi, pa, LDS_A);
                wmma::load_matrix_sync(fAlo, pa + SA_ELEMS, LDS_A);

                const __nv_bfloat16* pb = &sWhi[(ks * 16) * LDS_A + wc];
                wmma::load_matrix_sync(fBhi, pb, LDS_A);
                wmma::load_matrix_sync(fBlo, pb + SW_ELEMS, LDS_A);

                wmma::mma_sync(acc, fAhi, fBhi, acc);
                wmma::mma_sync(acc, fAhi, fBlo, acc);
                wmma::mma_sync(acc, fAlo, fBhi, acc);
            }

            #pragma unroll
            for (int e = 0; e < acc.num_elements; e++)
                acc.x[e] = fmaxf(acc.x[e], 0.0f);
            wmma::store_matrix_sync(
                &out[(long long)t * TILE_ROWS * D_DIM + wc],
                acc, D_DIM, wmma::mem_row_major);

            BAR_ARRIVE(NBUF + 1 + buf);         // signal buffer empty
        }
    }
}

extern "C" void kernel_launch(void* const* d_in, const int* in_sizes, int n_in,
                              void* d_out, int out_size)
{
    // Identify inputs by element count — robust to d_in ordering.
    int imax = 0, imin = 0;
    for (int i = 1; i < 3 && i < n_in; i++) {
        if (in_sizes[i] > in_sizes[imax]) imax = i;
        if (in_sizes[i] < in_sizes[imin]) imin = i;
    }
    const int imid = 3 - imax - imin;

    const float* features = (const float*)d_in[imax];
    const float* W        = (const float*)d_in[imin];
    const int*   sample   = (const int*)d_in[imid];

    float* out = (float*)d_out;

    cudaFuncSetAttribute(gcn_fused_kernel,
                         cudaFuncAttributeMaxDynamicSharedMemorySize,
                         SMEM_BYTES);

    gcn_fused_kernel<<<GRID, THREADS, SMEM_BYTES>>>(features, sample, W, out);
}